// round 17
// baseline (speedup 1.0000x reference)
#include <cuda_runtime.h>
#include <cooperative_groups.h>
#include <cstdint>

namespace cg = cooperative_groups;

#define NB 4
#define NS 8192
#define ND 512
#define NP 32
#define NT (NP + NS)          // 8224
#define LN_EPS 1e-5f
#define ZCH 256               // chunks per batch for reduce (32 rows each)
#define CROWS (NS / ZCH)      // 32
#define KZ 8                  // split-K for GEMVs
#define KS (ND / KZ)          // 64
#define NQ (ND / 4)           // 128 column-quads
#define NGRID 148
#define HBLK 74               // half-grid split for the duplex phase
#define WCH 257               // write chunks per batch (32 rows each)

// Scratch (device-side only)
__device__ float4 g_part4[ZCH][NB * NQ];  // per-chunk partial x sums (2MB)
__device__ float4 g_vp4[KZ][NB * NQ];     // split-K vbar partials
__device__ float4 g_yp4[KZ][NB * NQ];     // split-K y partials

__device__ __forceinline__ float4 f4add(float4 a, float4 b) {
    return make_float4(a.x + b.x, a.y + b.y, a.z + b.z, a.w + b.w);
}

// Reduce one 32-row chunk u (u in [0, 2*ZCH) over batch pair bp) -> g_part4
__device__ __forceinline__ void reduce_chunk(const float4* __restrict__ x4,
                                             int bp, int u, int d4) {
    const int b = bp + (u >> 8);
    const int z = u & (ZCH - 1);
    const float4* p = x4 + ((size_t)b * NS + (size_t)z * CROWS) * NQ + d4;
    float4 a[4];
#pragma unroll
    for (int j = 0; j < 4; j++) a[j] = make_float4(0.f, 0.f, 0.f, 0.f);
#pragma unroll
    for (int i = 0; i < CROWS; i += 16) {
        float4 v[16];
#pragma unroll
        for (int j = 0; j < 16; j++) v[j] = p[(size_t)(i + j) * NQ];
#pragma unroll
        for (int j = 0; j < 16; j++) {
            a[j & 3].x += v[j].x; a[j & 3].y += v[j].y;
            a[j & 3].z += v[j].z; a[j & 3].w += v[j].w;
        }
    }
    float4 r;
    r.x = (a[0].x + a[1].x) + (a[2].x + a[3].x);
    r.y = (a[0].y + a[1].y) + (a[2].y + a[3].y);
    r.z = (a[0].z + a[1].z) + (a[2].z + a[3].z);
    r.w = (a[0].w + a[1].w) + (a[2].w + a[3].w);
    g_part4[z][b * NQ + d4] = r;
}

// Write (broadcast) batch b using blocks [b0, b0+nb)
__device__ __forceinline__ void write_batch(const float4* __restrict__ bout4,
                                            float4* __restrict__ out4,
                                            int b, int bid, int b0, int nb,
                                            int tid) {
    const int q = tid & 127;
    float4 val = bout4[q];
#pragma unroll
    for (int z = 0; z < KZ; z++)
        val = f4add(val, g_yp4[z][b * NQ + q]);
    for (int c = bid - b0; c < WCH; c += nb) {
        float4* o = out4 + (size_t)b * NT * NQ + (size_t)c * (32 * NQ) + tid;
#pragma unroll
        for (int it = 0; it < 8; it++) {
            asm volatile("st.global.cs.v4.f32 [%0], {%1, %2, %3, %4};"
                         :: "l"(o + (size_t)it * 512),
                            "f"(val.x), "f"(val.y), "f"(val.z), "f"(val.w)
                         : "memory");
        }
    }
}

// GA: cbar slice + GEMV1 partial for (b, z)
__device__ __forceinline__ void do_GA(const float* __restrict__ pm,
                                      const float4* __restrict__ Wv4,
                                      int b, int z, int t,
                                      float (*spart)[KS], float* sk,
                                      float4 (*sacc)[NQ]) {
    {
        const int kl = t & 63, g = t >> 6;
        const int k  = z * KS + kl;
        const float* gp = (const float*)g_part4 + b * ND + k;
        float a = 0.f;
#pragma unroll 8
        for (int c = 0; c < ZCH / 8; c++)
            a += gp[(size_t)(g * (ZCH / 8) + c) * (NB * ND)];
#pragma unroll
        for (int p = 0; p < NP / 8; p++)
            a += pm[(g * (NP / 8) + p) * ND + k];
        spart[g][kl] = a;
    }
    __syncthreads();
    if (t < KS) {
        float a = 0.f;
#pragma unroll
        for (int g = 0; g < 8; g++) a += spart[g][t];
        sk[t] = a / (float)NT;
    }
    __syncthreads();
    {
        const int q = t & 127, s = t >> 7;
        const int k0 = z * KS + s * 16;
        float4 acc = make_float4(0.f, 0.f, 0.f, 0.f);
#pragma unroll
        for (int j = 0; j < 16; j++) {
            float4 w = Wv4[(size_t)(k0 + j) * NQ + q];
            float  c = sk[s * 16 + j];
            acc.x += c * w.x; acc.y += c * w.y; acc.z += c * w.z; acc.w += c * w.w;
        }
        sacc[s][q] = acc;
    }
    __syncthreads();
    if (t < NQ) {
        float4 r = f4add(f4add(sacc[0][t], sacc[1][t]),
                         f4add(sacc[2][t], sacc[3][t]));
        g_vp4[z][b * NQ + t] = r;
    }
    __syncthreads();
}

__device__ __forceinline__ float bsum512(float v, float* wred, float* bc) {
    const int t = threadIdx.x, lane = t & 31, wid = t >> 5;
#pragma unroll
    for (int off = 16; off > 0; off >>= 1)
        v += __shfl_xor_sync(0xffffffffu, v, off);
    if (lane == 0) wred[wid] = v;
    __syncthreads();
    if (wid == 0) {
        float s = (lane < 16) ? wred[lane] : 0.f;
#pragma unroll
        for (int off = 8; off > 0; off >>= 1)
            s += __shfl_xor_sync(0xffffffffu, s, off);
        if (lane == 0) *bc = s;
    }
    __syncthreads();
    return *bc;
}

// GB: vbar combine + LN + GEMV2 partial for (b, z)
__device__ __forceinline__ void do_GB(const float* __restrict__ bv,
                                      const float* __restrict__ gamma,
                                      const float* __restrict__ beta,
                                      const float4* __restrict__ Wout4,
                                      int b, int z, int t,
                                      float* ssn, float4 (*sacc)[NQ],
                                      float* wred, float* sbc) {
    float vb = bv[t];
#pragma unroll
    for (int c = 0; c < KZ; c++)
        vb += ((const float*)g_vp4[c])[b * ND + t];
    const float mu   = bsum512(vb, wred, &sbc[0]) / (float)ND;
    const float diff = vb - mu;
    const float var  = bsum512(diff * diff, wred, &sbc[1]) / (float)ND;
    const float inv  = rsqrtf(var + LN_EPS);
    const float nrm  = diff * inv * gamma[t] + beta[t];
    __syncthreads();
    if ((t >> 6) == z) ssn[t & 63] = nrm;
    __syncthreads();
    {
        const int q = t & 127, s = t >> 7;
        const int k0 = z * KS + s * 16;
        float4 acc = make_float4(0.f, 0.f, 0.f, 0.f);
#pragma unroll
        for (int j = 0; j < 16; j++) {
            float4 w = Wout4[(size_t)(k0 + j) * NQ + q];
            float  c = ssn[s * 16 + j];
            acc.x += c * w.x; acc.y += c * w.y; acc.z += c * w.z; acc.w += c * w.w;
        }
        sacc[s][q] = acc;
    }
    __syncthreads();
    if (t < NQ) {
        float4 r = f4add(f4add(sacc[0][t], sacc[1][t]),
                         f4add(sacc[2][t], sacc[3][t]));
        g_yp4[z][b * NQ + t] = r;
    }
    __syncthreads();
}

// ---------------------------------------------------------------------------
// S1 R(0,1) | S2 GA(0,1) | S3 GB(0,1) | S4 W(0,1)||R(2,3) | S5 GA(2,3)
// | S6 GB(2,3) | S7 W(2,3)
// ---------------------------------------------------------------------------
__global__ void __launch_bounds__(512, 1)
titan_fused_kernel(const float4* __restrict__ x4,
                   const float*  __restrict__ pm,
                   const float4* __restrict__ Wv4,
                   const float*  __restrict__ bv,
                   const float*  __restrict__ gamma,
                   const float*  __restrict__ beta,
                   const float4* __restrict__ Wout4,
                   const float4* __restrict__ bout4,
                   float4*       __restrict__ out4) {
    cg::grid_group grid = cg::this_grid();
    const int bid = blockIdx.x, tid = threadIdx.x;
    const int d4 = tid & 127, qr = tid >> 7;

    __shared__ float  spart[8][KS];
    __shared__ float  sk[KS];
    __shared__ float4 sacc[4][NQ];
    __shared__ float  ssn[KS];
    __shared__ float  wred[16], sbc[2];

    // S1: reduce batches 0,1 (512 chunk-units over 592 quarters)
    {
        const int u = qr * NGRID + bid;
        if (u < 2 * ZCH) reduce_chunk(x4, 0, u, d4);
    }
    grid.sync();

    // S2: GA(0,1) on 16 blocks
    if (bid < 16) do_GA(pm, Wv4, bid & 1, bid >> 1, tid, spart, sk, sacc);
    grid.sync();

    // S3: GB(0,1) on 16 blocks
    if (bid < 16) do_GB(bv, gamma, beta, Wout4, bid & 1, bid >> 1, tid,
                        ssn, sacc, wred, sbc);
    grid.sync();

    // S4: duplex — blocks [0,74) write batches 0,1; blocks [74,148) read 2,3
    if (bid < HBLK) {
        write_batch(bout4, out4, 0, bid, 0, HBLK, tid);
        write_batch(bout4, out4, 1, bid, 0, HBLK, tid);
    } else {
        for (int u = qr * HBLK + (bid - HBLK); u < 2 * ZCH; u += 4 * HBLK)
            reduce_chunk(x4, 2, u, d4);
    }
    grid.sync();

    // S5: GA(2,3) on 16 blocks
    if (bid < 16) do_GA(pm, Wv4, 2 + (bid & 1), bid >> 1, tid, spart, sk, sacc);
    grid.sync();

    // S6: GB(2,3) on 16 blocks
    if (bid < 16) do_GB(bv, gamma, beta, Wout4, 2 + (bid & 1), bid >> 1, tid,
                        ssn, sacc, wred, sbc);
    grid.sync();

    // S7: write batches 2,3 with all blocks
    write_batch(bout4, out4, 2, bid, 0, NGRID, tid);
    write_batch(bout4, out4, 3, bid, 0, NGRID, tid);
}

// ---------------------------------------------------------------------------
extern "C" void kernel_launch(void* const* d_in, const int* in_sizes, int n_in,
                              void* d_out, int out_size) {
    const float4* x4    = (const float4*)d_in[0];
    const float*  pm    = (const float*)d_in[1];
    // d_in[2]=Wk, [3]=bk, [6]=Wq, [7]=bq unused: softmax over zero-state and
    // constant-in-m logits collapse to uniform attention weights.
    const float4* Wv4   = (const float4*)d_in[4];
    const float*  bv    = (const float*)d_in[5];
    const float*  gamma = (const float*)d_in[8];
    const float*  beta  = (const float*)d_in[9];
    const float4* Wout4 = (const float4*)d_in[10];
    const float4* bout4 = (const float4*)d_in[11];
    float4*       out4  = (float4*)d_out;

    void* args[] = { (void*)&x4, (void*)&pm, (void*)&Wv4, (void*)&bv,
                     (void*)&gamma, (void*)&beta, (void*)&Wout4,
                     (void*)&bout4, (void*)&out4 };
    cudaLaunchCooperativeKernel((const void*)titan_fused_kernel,
                                dim3(NGRID), dim3(512), args, 0, 0);
}